// round 11
// baseline (speedup 1.0000x reference)
#include <cuda_runtime.h>

// TriMipEncoding: x [N,3] in [0,1], fm [3,512,512,16] fp32. out [N,48].
//
// R11 = R6 gather pattern exactly (8 front-batched LDG.128/thread, 16B lane
// requests — R10 proved wider lanes double L1 wavefronts), but the thread's
// two quad-units belong to the SAME (point,plane): quads c and c+2. One
// decode (x load + uv + clamp + weights) instead of two -> ALU and x-load
// instruction count halved at identical memory behavior.
// evict_last on fm, streaming stores.

#define PLANE_H 512
#define PLANE_W 512

__device__ __forceinline__ float4 ldg_resident(const float4* p, unsigned long long pol) {
    float4 v;
    asm("ld.global.nc.L2::cache_hint.v4.f32 {%0,%1,%2,%3}, [%4], %5;"
        : "=f"(v.x), "=f"(v.y), "=f"(v.z), "=f"(v.w)
        : "l"(p), "l"(pol));
    return v;
}

__device__ __forceinline__ float4 blend4(float w00, float w01, float w10, float w11,
                                         float4 a, float4 b, float4 d, float4 e) {
    float4 r;
    r.x = w00 * a.x + w01 * b.x + w10 * d.x + w11 * e.x;
    r.y = w00 * a.y + w01 * b.y + w10 * d.y + w11 * e.y;
    r.z = w00 * a.z + w01 * b.z + w10 * d.z + w11 * e.z;
    r.w = w00 * a.w + w01 * b.w + w10 * d.w + w11 * e.w;
    return r;
}

__global__ void __launch_bounds__(128) trimip_kernel(
    const float* __restrict__ x,
    const float4* __restrict__ fm4,
    float4* __restrict__ out4,
    int total)   // = n_pts * 6
{
    int idx = blockIdx.x * blockDim.x + threadIdx.x;
    if (idx >= total) return;

    unsigned long long pol;
    asm("createpolicy.fractional.L2::evict_last.b64 %0, 1.0;" : "=l"(pol));

    int h = idx & 1;         // quad pair: {0,2} or {1,3}
    int t = idx >> 1;        // (point, plane)
    int n = t / 3;           // magic-mul
    int p = t - n * 3;

    float x0 = __ldg(x + n * 3 + 0);
    float x1 = __ldg(x + n * 3 + 1);
    float x2 = __ldg(x + n * 3 + 2);

    // plane 0: (y,z) ; plane 1: (x,z) ; plane 2: (x,y)
    float cu = (p == 0) ? x1 : x0;
    float cv = (p == 2) ? x1 : x2;

    float u = cu * (float)PLANE_W - 0.5f;
    float v = cv * (float)PLANE_H - 0.5f;
    float i0f = floorf(u);
    float j0f = floorf(v);
    float fu = u - i0f;
    float fv = v - j0f;

    int i0 = min(max((int)i0f,     0), PLANE_W - 1);
    int i1 = min(max((int)i0f + 1, 0), PLANE_W - 1);
    int j0 = min(max((int)j0f,     0), PLANE_H - 1);
    int j1 = min(max((int)j0f + 1, 0), PLANE_H - 1);

    float w00 = (1.0f - fv) * (1.0f - fu);
    float w01 = (1.0f - fv) * fu;
    float w10 = fv * (1.0f - fu);
    float w11 = fv * fu;

    // float4 index of texel (j,i) in plane p, quad c: ((p*512 + j)*512 + i)*4 + c
    size_t plane_base = ((size_t)p << 20) + h;      // quad h ; second quad at +2
    size_t r0 = plane_base + (size_t)j0 * (PLANE_W * 4);
    size_t r1 = plane_base + (size_t)j1 * (PLANE_W * 4);
    const float4* a00 = fm4 + r0 + (size_t)i0 * 4;
    const float4* a01 = fm4 + r0 + (size_t)i1 * 4;
    const float4* a10 = fm4 + r1 + (size_t)i0 * 4;
    const float4* a11 = fm4 + r1 + (size_t)i1 * 4;

    // Front-batch 8 gathers: quads h and h+2 of the same 4 texels.
    float4 aA = ldg_resident(a00,     pol);
    float4 bA = ldg_resident(a01,     pol);
    float4 dA = ldg_resident(a10,     pol);
    float4 eA = ldg_resident(a11,     pol);
    float4 aB = ldg_resident(a00 + 2, pol);
    float4 bB = ldg_resident(a01 + 2, pol);
    float4 dB = ldg_resident(a10 + 2, pol);
    float4 eB = ldg_resident(a11 + 2, pol);

    // out float4 index: t*4 + quad  (quads h and h+2)
    __stcs(out4 + (size_t)t * 4 + h,     blend4(w00, w01, w10, w11, aA, bA, dA, eA));
    __stcs(out4 + (size_t)t * 4 + h + 2, blend4(w00, w01, w10, w11, aB, bB, dB, eB));
}

extern "C" void kernel_launch(void* const* d_in, const int* in_sizes, int n_in,
                              void* d_out, int out_size)
{
    const float*  x   = (const float*)d_in[0];    // [N,3]
    const float4* fm4 = (const float4*)d_in[1];   // [3,512,512,16] as float4
    float4* out4 = (float4*)d_out;                // [N,48] as float4

    int n_pts = in_sizes[0] / 3;
    int total = n_pts * 6;
    int threads = 128;
    int blocks = (total + threads - 1) / threads;
    trimip_kernel<<<blocks, threads>>>(x, fm4, out4, total);
}

// round 12
// speedup vs baseline: 1.2204x; 1.2204x over previous
#include <cuda_runtime.h>

// TriMipEncoding: x [N,3] in [0,1], fm [3,512,512,16] fp32. out [N,48].
//
// R12 = R6's exact memory mapping (unit = (point,plane,quad), c = idx&3 so
// 4 lanes x 16B cover each 64B texel -> minimal 12 gather wavefronts/point;
// proven optimal across R2/R10/R11), wrapped in a persistent grid-stride
// loop with a 2-stage software pipeline: next unit's 4 gathers are issued
// BEFORE blending the current unit, so every warp always has loads in
// flight. One wave of 148x16 blocks -> no CTA churn.

#define PLANE_H 512
#define PLANE_W 512

__device__ __forceinline__ float4 ldg_resident(const float4* p, unsigned long long pol) {
    float4 v;
    asm("ld.global.nc.L2::cache_hint.v4.f32 {%0,%1,%2,%3}, [%4], %5;"
        : "=f"(v.x), "=f"(v.y), "=f"(v.z), "=f"(v.w)
        : "l"(p), "l"(pol));
    return v;
}

struct Unit {
    const float4* a00; const float4* a01; const float4* a10; const float4* a11;
    float w00, w01, w10, w11;
};

__device__ __forceinline__ Unit decode(int idx, const float* __restrict__ x,
                                        const float4* __restrict__ fm4) {
    Unit un;
    int c = idx & 3;         // channel quad (4 lanes cover one 64B texel)
    int t = idx >> 2;        // (point, plane)
    int n = t / 3;           // magic-mul
    int p = t - n * 3;

    float x0 = __ldg(x + n * 3 + 0);
    float x1 = __ldg(x + n * 3 + 1);
    float x2 = __ldg(x + n * 3 + 2);

    // plane 0: (y,z) ; plane 1: (x,z) ; plane 2: (x,y)
    float cu = (p == 0) ? x1 : x0;
    float cv = (p == 2) ? x1 : x2;

    float u = cu * (float)PLANE_W - 0.5f;
    float v = cv * (float)PLANE_H - 0.5f;
    float i0f = floorf(u);
    float j0f = floorf(v);
    float fu = u - i0f;
    float fv = v - j0f;

    int i0 = min(max((int)i0f,     0), PLANE_W - 1);
    int i1 = min(max((int)i0f + 1, 0), PLANE_W - 1);
    int j0 = min(max((int)j0f,     0), PLANE_H - 1);
    int j1 = min(max((int)j0f + 1, 0), PLANE_H - 1);

    un.w00 = (1.0f - fv) * (1.0f - fu);
    un.w01 = (1.0f - fv) * fu;
    un.w10 = fv * (1.0f - fu);
    un.w11 = fv * fu;

    size_t plane_base = (size_t)p * PLANE_H * PLANE_W * 4 + c;
    size_t r0 = plane_base + (size_t)j0 * (PLANE_W * 4);
    size_t r1 = plane_base + (size_t)j1 * (PLANE_W * 4);
    un.a00 = fm4 + r0 + (size_t)i0 * 4;
    un.a01 = fm4 + r0 + (size_t)i1 * 4;
    un.a10 = fm4 + r1 + (size_t)i0 * 4;
    un.a11 = fm4 + r1 + (size_t)i1 * 4;
    return un;
}

__device__ __forceinline__ float4 blend(const Unit& un,
                                        float4 a, float4 b, float4 d, float4 e) {
    float4 r;
    r.x = un.w00 * a.x + un.w01 * b.x + un.w10 * d.x + un.w11 * e.x;
    r.y = un.w00 * a.y + un.w01 * b.y + un.w10 * d.y + un.w11 * e.y;
    r.z = un.w00 * a.z + un.w01 * b.z + un.w10 * d.z + un.w11 * e.z;
    r.w = un.w00 * a.w + un.w01 * b.w + un.w10 * d.w + un.w11 * e.w;
    return r;
}

__global__ void __launch_bounds__(128) trimip_kernel(
    const float* __restrict__ x,
    const float4* __restrict__ fm4,
    float4* __restrict__ out4,
    int total)   // = n_pts * 12
{
    int stride = gridDim.x * blockDim.x;
    int i = blockIdx.x * blockDim.x + threadIdx.x;
    if (i >= total) return;

    unsigned long long pol;
    asm("createpolicy.fractional.L2::evict_last.b64 %0, 1.0;" : "=l"(pol));

    // Prologue: issue loads for first unit
    Unit u = decode(i, x, fm4);
    float4 a = ldg_resident(u.a00, pol);
    float4 b = ldg_resident(u.a01, pol);
    float4 d = ldg_resident(u.a10, pol);
    float4 e = ldg_resident(u.a11, pol);

    // Pipelined mainloop: issue next unit's loads, then blend+store current.
    for (int j = i + stride; j < total; j += stride) {
        Unit un = decode(j, x, fm4);
        float4 an = ldg_resident(un.a00, pol);
        float4 bn = ldg_resident(un.a01, pol);
        float4 dn = ldg_resident(un.a10, pol);
        float4 en = ldg_resident(un.a11, pol);

        __stcs(out4 + i, blend(u, a, b, d, e));

        u = un; a = an; b = bn; d = dn; e = en; i = j;
    }
    __stcs(out4 + i, blend(u, a, b, d, e));
}

extern "C" void kernel_launch(void* const* d_in, const int* in_sizes, int n_in,
                              void* d_out, int out_size)
{
    const float*  x   = (const float*)d_in[0];    // [N,3]
    const float4* fm4 = (const float4*)d_in[1];   // [3,512,512,16] as float4
    float4* out4 = (float4*)d_out;                // [N,48] as float4

    int n_pts = in_sizes[0] / 3;
    int total = n_pts * 12;
    int threads = 128;
    int blocks = 148 * 16;                         // one full wave, 64 warps/SM
    int needed = (total + threads - 1) / threads;
    if (blocks > needed) blocks = needed;
    trimip_kernel<<<blocks, threads>>>(x, fm4, out4, total);
}

// round 13
// speedup vs baseline: 1.4618x; 1.1978x over previous
#include <cuda_runtime.h>

// TriMipEncoding: x [N,3] in [0,1], fm [3,512,512,16] fp32. out [N,48].
//
// R13 = R6 VERBATIM (best: 58.1us) with one change: __launch_bounds__(128, 8).
// Every MLP attempt (R7/R8/R12) died the same way: ptxas pins regs at 32
// (targeting 16 blocks/SM) and re-serializes the load batch to ~4-5 live
// loads. minnctapersm=8 raises the per-thread reg budget to 64, letting the
// 8-load batch stay fully live: 32 warps x 8 = 256 outstanding loads/SM
// (vs ~204 effective in R6 at 54 warps x ~4).
// Gather mapping (c = idx&3, 16B lanes covering whole 64B texels) is the
// proven wavefront minimum - untouched.

#define PLANE_H 512
#define PLANE_W 512

__device__ __forceinline__ float4 ldg_resident(const float4* p, unsigned long long pol) {
    float4 v;
    asm("ld.global.nc.L2::cache_hint.v4.f32 {%0,%1,%2,%3}, [%4], %5;"
        : "=f"(v.x), "=f"(v.y), "=f"(v.z), "=f"(v.w)
        : "l"(p), "l"(pol));
    return v;
}

struct Unit {
    const float4* a00; const float4* a01; const float4* a10; const float4* a11;
    float w00, w01, w10, w11;
};

__device__ __forceinline__ Unit decode(int idx, const float* __restrict__ x,
                                        const float4* __restrict__ fm4) {
    Unit un;
    int c = idx & 3;
    int t = idx >> 2;
    int n = t / 3;           // magic-mul
    int p = t - n * 3;

    float x0 = __ldg(x + n * 3 + 0);
    float x1 = __ldg(x + n * 3 + 1);
    float x2 = __ldg(x + n * 3 + 2);

    float cu = (p == 0) ? x1 : x0;
    float cv = (p == 2) ? x1 : x2;

    float u = cu * (float)PLANE_W - 0.5f;
    float v = cv * (float)PLANE_H - 0.5f;
    float i0f = floorf(u);
    float j0f = floorf(v);
    float fu = u - i0f;
    float fv = v - j0f;

    int i0 = min(max((int)i0f,     0), PLANE_W - 1);
    int i1 = min(max((int)i0f + 1, 0), PLANE_W - 1);
    int j0 = min(max((int)j0f,     0), PLANE_H - 1);
    int j1 = min(max((int)j0f + 1, 0), PLANE_H - 1);

    un.w00 = (1.0f - fv) * (1.0f - fu);
    un.w01 = (1.0f - fv) * fu;
    un.w10 = fv * (1.0f - fu);
    un.w11 = fv * fu;

    size_t plane_base = (size_t)p * PLANE_H * PLANE_W * 4 + c;
    size_t r0 = plane_base + (size_t)j0 * (PLANE_W * 4);
    size_t r1 = plane_base + (size_t)j1 * (PLANE_W * 4);
    un.a00 = fm4 + r0 + (size_t)i0 * 4;
    un.a01 = fm4 + r0 + (size_t)i1 * 4;
    un.a10 = fm4 + r1 + (size_t)i0 * 4;
    un.a11 = fm4 + r1 + (size_t)i1 * 4;
    return un;
}

__device__ __forceinline__ float4 blend(const Unit& un,
                                        float4 a, float4 b, float4 d, float4 e) {
    float4 r;
    r.x = un.w00 * a.x + un.w01 * b.x + un.w10 * d.x + un.w11 * e.x;
    r.y = un.w00 * a.y + un.w01 * b.y + un.w10 * d.y + un.w11 * e.y;
    r.z = un.w00 * a.z + un.w01 * b.z + un.w10 * d.z + un.w11 * e.z;
    r.w = un.w00 * a.w + un.w01 * b.w + un.w10 * d.w + un.w11 * e.w;
    return r;
}

__global__ void __launch_bounds__(128, 8) trimip_kernel(
    const float* __restrict__ x,
    const float4* __restrict__ fm4,
    float4* __restrict__ out4,
    int half)   // = n_pts * 6 ; unit1 = idx + half
{
    int idx = blockIdx.x * blockDim.x + threadIdx.x;
    if (idx >= half) return;

    unsigned long long pol;
    asm("createpolicy.fractional.L2::evict_last.b64 %0, 1.0;" : "=l"(pol));

    Unit u0 = decode(idx,        x, fm4);
    Unit u1 = decode(idx + half, x, fm4);

    // Front-batch all 8 gathers (now with reg budget to keep them live)
    float4 a0 = ldg_resident(u0.a00, pol);
    float4 b0 = ldg_resident(u0.a01, pol);
    float4 d0 = ldg_resident(u0.a10, pol);
    float4 e0 = ldg_resident(u0.a11, pol);
    float4 a1 = ldg_resident(u1.a00, pol);
    float4 b1 = ldg_resident(u1.a01, pol);
    float4 d1 = ldg_resident(u1.a10, pol);
    float4 e1 = ldg_resident(u1.a11, pol);

    __stcs(out4 + idx,        blend(u0, a0, b0, d0, e0));
    __stcs(out4 + idx + half, blend(u1, a1, b1, d1, e1));
}

extern "C" void kernel_launch(void* const* d_in, const int* in_sizes, int n_in,
                              void* d_out, int out_size)
{
    const float*  x   = (const float*)d_in[0];    // [N,3]
    const float4* fm4 = (const float4*)d_in[1];   // [3,512,512,16] as float4
    float4* out4 = (float4*)d_out;                // [N,48] as float4

    int n_pts = in_sizes[0] / 3;
    int half = n_pts * 6;                          // n_pts*12 / 2
    int threads = 128;
    int blocks = (half + threads - 1) / threads;
    trimip_kernel<<<blocks, threads>>>(x, fm4, out4, half);
}

// round 14
// speedup vs baseline: 1.5766x; 1.0786x over previous
#include <cuda_runtime.h>

// TriMipEncoding: x [N,3] in [0,1], fm [3,512,512,16] fp32. out [N,48].
//
// FINAL (= R6, session best 58.1us): 4 threads per (point,plane), one float4
// channel-quad each (c = idx&3 -> 4 lanes x 16B cover a whole 64B texel =
// minimal 12 gather line-visits/point; proven optimal vs R1/R9/R10/R11).
// Each thread processes 2 strided units with 8 front-batched LDG.128.
// evict_last keeps the 50MB planes L2-resident; __stcs streams the output.
// Measured at the calibrated L1TEX wavefront floor (~15 wf/pt @ ~72% pipe
// ceiling): further restructures (MLP, shuffles, wide loads, persistent
// pipelines, launch-bounds) were all bench-refuted in R7-R13.

#define PLANE_H 512
#define PLANE_W 512

__device__ __forceinline__ float4 ldg_resident(const float4* p, unsigned long long pol) {
    float4 v;
    asm("ld.global.nc.L2::cache_hint.v4.f32 {%0,%1,%2,%3}, [%4], %5;"
        : "=f"(v.x), "=f"(v.y), "=f"(v.z), "=f"(v.w)
        : "l"(p), "l"(pol));
    return v;
}

struct Unit {
    const float4* a00; const float4* a01; const float4* a10; const float4* a11;
    float w00, w01, w10, w11;
};

__device__ __forceinline__ Unit decode(int idx, const float* __restrict__ x,
                                        const float4* __restrict__ fm4) {
    Unit un;
    int c = idx & 3;
    int t = idx >> 2;
    int n = t / 3;           // magic-mul
    int p = t - n * 3;

    float x0 = __ldg(x + n * 3 + 0);
    float x1 = __ldg(x + n * 3 + 1);
    float x2 = __ldg(x + n * 3 + 2);

    // plane 0: (y,z) ; plane 1: (x,z) ; plane 2: (x,y)
    float cu = (p == 0) ? x1 : x0;
    float cv = (p == 2) ? x1 : x2;

    float u = cu * (float)PLANE_W - 0.5f;
    float v = cv * (float)PLANE_H - 0.5f;
    float i0f = floorf(u);
    float j0f = floorf(v);
    float fu = u - i0f;
    float fv = v - j0f;

    int i0 = min(max((int)i0f,     0), PLANE_W - 1);
    int i1 = min(max((int)i0f + 1, 0), PLANE_W - 1);
    int j0 = min(max((int)j0f,     0), PLANE_H - 1);
    int j1 = min(max((int)j0f + 1, 0), PLANE_H - 1);

    un.w00 = (1.0f - fv) * (1.0f - fu);
    un.w01 = (1.0f - fv) * fu;
    un.w10 = fv * (1.0f - fu);
    un.w11 = fv * fu;

    size_t plane_base = (size_t)p * PLANE_H * PLANE_W * 4 + c;
    size_t r0 = plane_base + (size_t)j0 * (PLANE_W * 4);
    size_t r1 = plane_base + (size_t)j1 * (PLANE_W * 4);
    un.a00 = fm4 + r0 + (size_t)i0 * 4;
    un.a01 = fm4 + r0 + (size_t)i1 * 4;
    un.a10 = fm4 + r1 + (size_t)i0 * 4;
    un.a11 = fm4 + r1 + (size_t)i1 * 4;
    return un;
}

__device__ __forceinline__ float4 blend(const Unit& un,
                                        float4 a, float4 b, float4 d, float4 e) {
    float4 r;
    r.x = un.w00 * a.x + un.w01 * b.x + un.w10 * d.x + un.w11 * e.x;
    r.y = un.w00 * a.y + un.w01 * b.y + un.w10 * d.y + un.w11 * e.y;
    r.z = un.w00 * a.z + un.w01 * b.z + un.w10 * d.z + un.w11 * e.z;
    r.w = un.w00 * a.w + un.w01 * b.w + un.w10 * d.w + un.w11 * e.w;
    return r;
}

__global__ void __launch_bounds__(128) trimip_kernel(
    const float* __restrict__ x,
    const float4* __restrict__ fm4,
    float4* __restrict__ out4,
    int half)   // = n_pts * 6 ; unit1 = idx + half
{
    int idx = blockIdx.x * blockDim.x + threadIdx.x;
    if (idx >= half) return;

    unsigned long long pol;
    asm("createpolicy.fractional.L2::evict_last.b64 %0, 1.0;" : "=l"(pol));

    Unit u0 = decode(idx,        x, fm4);
    Unit u1 = decode(idx + half, x, fm4);

    // Front-batch all 8 gathers
    float4 a0 = ldg_resident(u0.a00, pol);
    float4 b0 = ldg_resident(u0.a01, pol);
    float4 d0 = ldg_resident(u0.a10, pol);
    float4 e0 = ldg_resident(u0.a11, pol);
    float4 a1 = ldg_resident(u1.a00, pol);
    float4 b1 = ldg_resident(u1.a01, pol);
    float4 d1 = ldg_resident(u1.a10, pol);
    float4 e1 = ldg_resident(u1.a11, pol);

    __stcs(out4 + idx,        blend(u0, a0, b0, d0, e0));
    __stcs(out4 + idx + half, blend(u1, a1, b1, d1, e1));
}

extern "C" void kernel_launch(void* const* d_in, const int* in_sizes, int n_in,
                              void* d_out, int out_size)
{
    const float*  x   = (const float*)d_in[0];    // [N,3]
    const float4* fm4 = (const float4*)d_in[1];   // [3,512,512,16] as float4
    float4* out4 = (float4*)d_out;                // [N,48] as float4

    int n_pts = in_sizes[0] / 3;
    int half = n_pts * 6;                          // n_pts*12 / 2
    int threads = 128;
    int blocks = (half + threads - 1) / threads;
    trimip_kernel<<<blocks, threads>>>(x, fm4, out4, half);
}